// round 16
// baseline (speedup 1.0000x reference)
#include <cuda_runtime.h>
#include <cuda_bf16.h>
#include <math.h>
#include <stdint.h>

#define LT   4
#define BB   8
#define LL   1024
#define DIM  256
#define NROWS (LT*BB*LL)     // 32768
#define HEADS 8
#define HD    32
#define RS    64
#define RR    16
#define NTOPK 4
#define QKVC  768
#define HID   1024

// ---------------- scratch ----------------------------------------------------
__device__ unsigned g_mask[NROWS*8];            // spike bitmasks (256 bits/row)
__device__ __nv_bfloat16 g_qkvb[NROWS*QKVC];    // q|k|v in bf16
__device__ float g_qr  [LT*BB*RR*DIM];
__device__ float g_kr  [LT*BB*RR*DIM];
__device__ int   g_idx [LT*BB*RR*NTOPK];
__device__ __nv_bfloat16 g_attn[NROWS*DIM];
__device__ float g_x1  [NROWS*DIM];
__device__ __nv_bfloat16 g_h   [NROWS*HID];
__device__ __nv_bfloat16 g_w1bf[DIM*HID];
__device__ __nv_bfloat16 g_wobf[DIM*DIM];
__device__ __nv_bfloat16 g_w2bf[HID*DIM];
__device__ float g_psum[512*DIM];
__device__ float g_psq [512*DIM];
__device__ float g_mean[DIM];
__device__ float g_var [DIM];

__device__ __forceinline__ uint32_t pk2(float a, float b) {
    __nv_bfloat162 h = __floats2bfloat162_rn(a, b);
    return *(uint32_t*)&h;
}
__device__ __forceinline__ uint32_t smem_u32(const void* p) {
    return (uint32_t)__cvta_generic_to_shared(p);
}

// ---------------- batchnorm stats (512 blocks x 64 rows) --------------------
__global__ void stats1(const float* __restrict__ in) {
    int blk = blockIdx.x, d = threadIdx.x;
    float s = 0.f, sq = 0.f;
    int r0 = blk * 64;
    for (int i = 0; i < 64; i++) {
        float v = in[(size_t)(r0 + i) * DIM + d];
        s += v; sq += v * v;
    }
    g_psum[blk*DIM + d] = s;
    g_psq [blk*DIM + d] = sq;
}

// parallel final reduce: one block per channel d, folds 512 partials
__global__ void stats2() {
    int d = blockIdx.x, t = threadIdx.x;
    __shared__ float ss[256];
    __shared__ float sq[256];
    ss[t] = g_psum[t*DIM + d] + g_psum[(t+256)*DIM + d];
    sq[t] = g_psq [t*DIM + d] + g_psq [(t+256)*DIM + d];
    __syncthreads();
    #pragma unroll
    for (int o = 128; o > 0; o >>= 1) {
        if (t < o) { ss[t] += ss[t + o]; sq[t] += sq[t + o]; }
        __syncthreads();
    }
    if (t == 0) {
        float mu = ss[0] / (float)NROWS;
        float var = sq[0] / (float)NROWS - mu * mu;
        g_mean[d] = mu;
        g_var[d]  = var > 0.f ? var : 0.f;
    }
}

// ---------------- batchnorm + LIF -> spike bitmask ---------------------------
__global__ void bnlif(const float* __restrict__ in,
                      const float* __restrict__ gamma,
                      const float* __restrict__ beta) {
    int tid = blockIdx.x * 256 + threadIdx.x;
    int d = tid & 255;
    int n = tid >> 8;
    float mu = g_mean[d];
    float iv = 1.0f / sqrtf(g_var[d] + 1e-5f);
    float ga = gamma[d], be = beta[d];
    const size_t stride = (size_t)BB * LL * DIM;
    size_t base = (size_t)tid;
    float v = 0.f;
    #pragma unroll
    for (int t = 0; t < LT; t++) {
        float xt = (in[base + t*stride] - mu) * iv * ga + be;
        v += (xt - v) * 0.5f;
        bool sp = (v >= 1.0f);
        unsigned m = __ballot_sync(0xffffffffu, sp);
        if (sp) v = 0.f;
        if ((d & 31) == 0)
            g_mask[((size_t)(t*8192 + n))*8 + (d >> 5)] = m;
    }
}

// ---------------- fp32 -> bf16 weight conversion ----------------------------
__global__ void cvtW(const float* __restrict__ src, __nv_bfloat16* __restrict__ dst) {
    int i = blockIdx.x * 256 + threadIdx.x;
    float4 v = ((const float4*)src)[i];
    uint2 o;
    o.x = pk2(v.x, v.y);
    o.y = pk2(v.z, v.w);
    ((uint2*)dst)[i] = o;
}

// ---------------- shared list-build from mask --------------------------------
__device__ __forceinline__ int build_list(int n, int tid, int* list,
                                          unsigned* masks, int* offs) {
    int warp = tid >> 5, lane = tid & 31;
    unsigned m = g_mask[(size_t)n * 8 + warp];
    if (lane == 0) masks[warp] = m;
    __syncthreads();
    if (tid == 0) {
        int o = 0;
        #pragma unroll
        for (int w = 0; w < 8; w++) { offs[w] = o; o += __popc(masks[w]); }
        offs[8] = o;
    }
    __syncthreads();
    if ((m >> lane) & 1)
        list[offs[warp] + __popc(m & ((1u << lane) - 1u))] = tid;
    int cnt = offs[8];
    __syncthreads();
    return cnt;
}

// ---------------- sparse binary GEMM: qkv (fp32 W gather, bf16 out) ---------
__global__ void spgemm_qkv(const float* __restrict__ W,
                           const float* __restrict__ bias) {
    int n = blockIdx.x, tid = threadIdx.x;
    __shared__ int list[256];
    __shared__ unsigned masks[8];
    __shared__ int offs[9];
    int cnt = build_list(n, tid, list, masks, offs);

    if (tid < 192) {
        const float4* W4 = (const float4*)W;
        float4 acc = ((const float4*)bias)[tid];
        for (int i = 0; i < cnt; i++) {
            float4 w = W4[(size_t)list[i] * 192 + tid];
            acc.x += w.x; acc.y += w.y; acc.z += w.z; acc.w += w.w;
        }
        uint2 o;
        o.x = pk2(acc.x, acc.y);
        o.y = pk2(acc.z, acc.w);
        ((uint2*)(g_qkvb + (size_t)n * QKVC))[tid] = o;
    }
}

// ---------------- sparse binary GEMM: MLP (bf16 W, bf16 out, gelu) ----------
__global__ void spgemm_mlp(const float* __restrict__ bias,
                           __nv_bfloat16* __restrict__ out) {
    int n = blockIdx.x, tid = threadIdx.x;
    __shared__ int list[256];
    __shared__ unsigned masks[8];
    __shared__ int offs[9];
    int cnt = build_list(n, tid, list, masks, offs);

    float4 bv = ((const float4*)bias)[tid];
    float a0 = bv.x, a1 = bv.y, a2 = bv.z, a3 = bv.w;
    for (int i = 0; i < cnt; i++) {
        uint2 w = *(const uint2*)(g_w1bf + (size_t)list[i] * HID + tid * 4);
        float2 f0 = __bfloat1622float2(*(__nv_bfloat162*)&w.x);
        float2 f1 = __bfloat1622float2(*(__nv_bfloat162*)&w.y);
        a0 += f0.x; a1 += f0.y; a2 += f1.x; a3 += f1.y;
    }
    a0 = 0.5f*a0*(1.f + erff(a0*0.70710678118654752f));
    a1 = 0.5f*a1*(1.f + erff(a1*0.70710678118654752f));
    a2 = 0.5f*a2*(1.f + erff(a2*0.70710678118654752f));
    a3 = 0.5f*a3*(1.f + erff(a3*0.70710678118654752f));
    uint2 o;
    o.x = pk2(a0, a1);
    o.y = pk2(a2, a3);
    ((uint2*)(out + (size_t)n * HID))[tid] = o;
}

// ---------------- region q/k means from spike counts (exact fp32) -----------
__global__ void regqk(const float* __restrict__ Wqkv,
                      const float* __restrict__ bqkv) {
    int blk = blockIdx.x, tid = threadIdx.x;
    int tb = blk >> 1, half = blk & 1;
    __shared__ unsigned words[8][64][8];   // 16 KB
    __shared__ float cntf[8][256];         // 8 KB
    int base_row = tb * 1024 + half * 512;
    for (int i = tid; i < 4096; i += 256) {
        int r = i >> 9, rem = i & 511, row = rem >> 3, w = rem & 7;
        words[r][row][w] = g_mask[(size_t)(base_row + r*64 + row)*8 + w];
    }
    __syncthreads();
    int wsel = tid >> 5, bit = tid & 31;
    #pragma unroll
    for (int r = 0; r < 8; r++) {
        int c = 0;
        #pragma unroll 16
        for (int i = 0; i < 64; i++) c += (words[r][i][wsel] >> bit) & 1;
        cntf[r][tid] = (float)c;
    }
    __syncthreads();
    float aq[8], ak[8];
    #pragma unroll
    for (int r = 0; r < 8; r++) { aq[r] = 0.f; ak[r] = 0.f; }
    for (int d = 0; d < 256; d++) {
        float wq = Wqkv[d*QKVC + tid];
        float wk = Wqkv[d*QKVC + 256 + tid];
        #pragma unroll
        for (int r = 0; r < 8; r++) {
            float c = cntf[r][d];
            aq[r] = fmaf(c, wq, aq[r]);
            ak[r] = fmaf(c, wk, ak[r]);
        }
    }
    float bq = bqkv[tid], bk = bqkv[256 + tid];
    #pragma unroll
    for (int r = 0; r < 8; r++) {
        int reg = tb*16 + half*8 + r;
        g_qr[reg*256 + tid] = aq[r]*(1.f/64.f) + bq;
        g_kr[reg*256 + tid] = ak[r]*(1.f/64.f) + bk;
    }
}

// ---------------- region affinity + top-k -----------------------------------
__global__ void afftopk() {
    __shared__ float qs[16][257];
    __shared__ float ks[16][257];
    __shared__ float aff[16][17];
    int tb = blockIdx.x, tid = threadIdx.x;
    for (int idx = tid; idx < 16*256; idx += 256) {
        int rr = idx >> 8, d = idx & 255;
        qs[rr][d] = g_qr[(tb*16 + rr)*DIM + d];
        ks[rr][d] = g_kr[(tb*16 + rr)*DIM + d];
    }
    __syncthreads();
    int r = tid >> 4, s = tid & 15;
    float a = 0.f;
    #pragma unroll 8
    for (int d = 0; d < 256; d++) a += qs[r][d] * ks[s][d];
    aff[r][s] = a;
    __syncthreads();
    if (tid < 16) {
        float vals[16];
        #pragma unroll
        for (int s2 = 0; s2 < 16; s2++) vals[s2] = aff[tid][s2];
        #pragma unroll
        for (int m = 0; m < NTOPK; m++) {
            int best = 0; float bv = vals[0];
            #pragma unroll
            for (int s2 = 1; s2 < 16; s2++)
                if (vals[s2] > bv) { bv = vals[s2]; best = s2; }
            g_idx[(tb*16 + tid)*NTOPK + m] = best;
            vals[best] = -1e30f;
        }
    }
}

// ---------------- bf16 mma --------------------------------------------------
__device__ __forceinline__ void mma_bf16(float* d, const uint32_t* a, const uint32_t* b) {
    asm volatile(
        "mma.sync.aligned.m16n8k16.row.col.f32.bf16.bf16.f32 "
        "{%0,%1,%2,%3}, {%4,%5,%6,%7}, {%8,%9}, {%0,%1,%2,%3};\n"
        : "+f"(d[0]), "+f"(d[1]), "+f"(d[2]), "+f"(d[3])
        : "r"(a[0]), "r"(a[1]), "r"(a[2]), "r"(a[3]), "r"(b[0]), "r"(b[1]));
}

// exp(s/sqrt(32)) via exp2, degree-4, FMA-pipe only
__device__ __forceinline__ float fexp_sc(float s) {
    const float C = 0.17677669529663687f * 1.4426950408889634f;
    float y = s * C;
    float z = y + 12582912.f;
    float n = z - 12582912.f;
    float f = y - n;
    float p = 0.0096181291f;
    p = fmaf(p, f, 0.0555041087f);
    p = fmaf(p, f, 0.2402265069f);
    p = fmaf(p, f, 0.6931471806f);
    p = fmaf(p, f, 1.0f);
    return __int_as_float(__float_as_int(p) + (__float_as_int(z) << 23));
}

// ---------------- bi-level attention (tensor cores, bf16 in/out) ------------
__global__ void attn_mma() {
    int bid = blockIdx.x;
    int h  = bid & 7;
    int r  = (bid >> 3) & 15;
    int tb = bid >> 7;
    int t = threadIdx.x, lane = t & 31, w = t >> 5;

    __shared__ __nv_bfloat16 Ks[64*40];
    __shared__ __nv_bfloat16 Vt[32*72];

    int rlo  = lane >> 2;
    int qcol = (lane & 3) * 2;

    uint32_t qf[2][2][4];
    int qr_base = tb * LL + r * RS + w * 32;
    #pragma unroll
    for (int mt = 0; mt < 2; mt++) {
        #pragma unroll
        for (int kt = 0; kt < 2; kt++) {
            const __nv_bfloat16* qp = g_qkvb + (size_t)(qr_base + mt*16 + rlo) * QKVC + h*HD + kt*16 + qcol;
            qf[mt][kt][0] = *(const uint32_t*)(qp);
            qf[mt][kt][1] = *(const uint32_t*)(qp + 8*QKVC);
            qf[mt][kt][2] = *(const uint32_t*)(qp + 8);
            qf[mt][kt][3] = *(const uint32_t*)(qp + 8*QKVC + 8);
        }
    }

    float oacc[2][4][4];
    #pragma unroll
    for (int mt = 0; mt < 2; mt++)
        #pragma unroll
        for (int nt = 0; nt < 4; nt++)
            #pragma unroll
            for (int q = 0; q < 4; q++) oacc[mt][nt][q] = 0.f;
    float rs[2][2] = {{0.f,0.f},{0.f,0.f}};

    for (int reg = 0; reg < NTOPK; reg++) {
        int s = g_idx[(tb*RR + r)*NTOPK + reg];
        int kvbase = tb * LL + s * RS;
        #pragma unroll
        for (int i = 0; i < 16; i++) {
            int flat = i*64 + t;
            int j  = flat >> 4;
            int d2 = (flat & 15) * 2;
            const __nv_bfloat16* kp = g_qkvb + (size_t)(kvbase + j)*QKVC + DIM + h*HD + d2;
            uint32_t kv = *(const uint32_t*)kp;
            uint32_t vv = *(const uint32_t*)(kp + DIM);
            *(uint32_t*)&Ks[j*40 + d2] = kv;
            __nv_bfloat162 v2 = *(__nv_bfloat162*)&vv;
            Vt[d2*72 + j]     = v2.x;
            Vt[(d2+1)*72 + j] = v2.y;
        }
        __syncthreads();

        float sacc[2][8][4];
        #pragma unroll
        for (int mt = 0; mt < 2; mt++)
            #pragma unroll
            for (int nt = 0; nt < 8; nt++)
                #pragma unroll
                for (int q = 0; q < 4; q++) sacc[mt][nt][q] = 0.f;

        #pragma unroll
        for (int kt = 0; kt < 2; kt++) {
            #pragma unroll
            for (int nt = 0; nt < 8; nt++) {
                int j = nt*8 + rlo;
                int a0 = j*40 + kt*16 + qcol;
                uint32_t b0 = *(uint32_t*)&Ks[a0];
                uint32_t b1 = *(uint32_t*)&Ks[a0 + 8];
                uint32_t bfr[2] = {b0, b1};
                mma_bf16(sacc[0][nt], qf[0][kt], bfr);
                mma_bf16(sacc[1][nt], qf[1][kt], bfr);
            }
        }

        uint32_t pf[2][4][4];
        #pragma unroll
        for (int mt = 0; mt < 2; mt++) {
            #pragma unroll
            for (int nt = 0; nt < 8; nt++) {
                float e0 = fexp_sc(sacc[mt][nt][0]);
                float e1 = fexp_sc(sacc[mt][nt][1]);
                float e2 = fexp_sc(sacc[mt][nt][2]);
                float e3 = fexp_sc(sacc[mt][nt][3]);
                rs[mt][0] += e0 + e1;
                rs[mt][1] += e2 + e3;
                int kt2 = nt >> 1;
                if ((nt & 1) == 0) {
                    pf[mt][kt2][0] = pk2(e0, e1);
                    pf[mt][kt2][1] = pk2(e2, e3);
                } else {
                    pf[mt][kt2][2] = pk2(e0, e1);
                    pf[mt][kt2][3] = pk2(e2, e3);
                }
            }
        }

        #pragma unroll
        for (int kt2 = 0; kt2 < 4; kt2++) {
            #pragma unroll
            for (int nv = 0; nv < 4; nv++) {
                int d = nv*8 + rlo;
                int j0 = kt2*16 + qcol;
                uint32_t b0 = *(uint32_t*)&Vt[d*72 + j0];
                uint32_t b1 = *(uint32_t*)&Vt[d*72 + j0 + 8];
                uint32_t bfr[2] = {b0, b1};
                mma_bf16(oacc[0][nv], pf[0][kt2], bfr);
                mma_bf16(oacc[1][nv], pf[1][kt2], bfr);
            }
        }
        __syncthreads();
    }

    #pragma unroll
    for (int mt = 0; mt < 2; mt++)
        #pragma unroll
        for (int i = 0; i < 2; i++) {
            float v = rs[mt][i];
            v += __shfl_xor_sync(0xffffffffu, v, 1);
            v += __shfl_xor_sync(0xffffffffu, v, 2);
            rs[mt][i] = 1.f / v;
        }

    #pragma unroll
    for (int mt = 0; mt < 2; mt++) {
        int row0 = qr_base + mt*16 + rlo;
        #pragma unroll
        for (int nv = 0; nv < 4; nv++) {
            int d = h*HD + nv*8 + qcol;
            *(uint32_t*)(g_attn + (size_t)row0*DIM + d) =
                pk2(oacc[mt][nv][0]*rs[mt][0], oacc[mt][nv][1]*rs[mt][0]);
            *(uint32_t*)(g_attn + (size_t)(row0+8)*DIM + d) =
                pk2(oacc[mt][nv][2]*rs[mt][1], oacc[mt][nv][3]*rs[mt][1]);
        }
    }
}

// ---------------- bf16 tensor-core GEMM, double-buffered smem ----------------
// out[M,256] = res + scale * (A_bf16[M,K] @ B_bf16[K,256] + bias)
__global__ void gemm_bf16_res(const __nv_bfloat16* __restrict__ A,
                              const __nv_bfloat16* __restrict__ B,
                              const float* __restrict__ bias,
                              const float* __restrict__ res,
                              const float* __restrict__ scale_p,
                              float* __restrict__ out,
                              int K) {
    __shared__ __align__(16) __nv_bfloat16 As[2][128*40];
    __shared__ __align__(16) __nv_bfloat16 Bs[2][32*136];
    int t = threadIdx.x;
    int lane = t & 31, warp = t >> 5;
    int wm = warp & 3;
    int wn = warp >> 2;
    int row0 = blockIdx.y * 128, col0 = blockIdx.x * 128;

    float acc[2][8][4];
    #pragma unroll
    for (int mt = 0; mt < 2; mt++)
        #pragma unroll
        for (int nt = 0; nt < 8; nt++)
            #pragma unroll
            for (int q = 0; q < 4; q++) acc[mt][nt][q] = 0.f;

    const __nv_bfloat16* Ag = A + (size_t)row0 * K;
    const __nv_bfloat16* Bg = B + col0;

    int a_r  = t >> 2, a_j = t & 3;          // A: row, 8-col group
    int b_k  = t >> 5, b_c = t & 31;         // B: k-row, 4-col group

    // preload tile 0 into buffer 0
    {
        uint4 pa[2];
        uint2 pb[4];
        #pragma unroll
        for (int i = 0; i < 2; i++)
            pa[i] = *(const uint4*)(Ag + (size_t)(a_r + i*64)*K + a_j*8);
        #pragma unroll
        for (int i = 0; i < 4; i++)
            pb[i] = *(const uint2*)(Bg + (size_t)(b_k + i*8)*256 + b_c*4);
        #pragma unroll
        for (int i = 0; i < 2; i++)
            *(uint4*)((uint32_t*)As[0] + (a_r + i*64)*20 + a_j*4) = pa[i];
        #pragma unroll
        for (int i = 0; i < 4; i++)
            *(uint2*)((uint32_t*)Bs[0] + (b_k + i*8)*68 + b_c*2) = pb[i];
    }
    __syncthreads();

    int nkt = K >> 5;
    for (int kt = 0; kt < nkt; kt++) {
        int cur = kt & 1, nxt = cur ^ 1;
        uint4 pa[2];
        uint2 pb[4];
        bool have_next = (kt + 1 < nkt);
        if (have_next) {
            int k0 = (kt + 1) * 32;
            #pragma unroll
            for (int i = 0; i < 2; i++)
                pa[i] = *(const uint4*)(Ag + (size_t)(a_r + i*64)*K + k0 + a_j*8);
            #pragma unroll
            for (int i = 0; i < 4; i++)
                pb[i] = *(const uint2*)(Bg + (size_t)(k0 + b_k + i*8)*256 + b_c*4);
        }
        // compute on current buffer (hides next-tile LDG latency)
        #pragma unroll
        for (int ks = 0; ks < 2; ks++) {
            uint32_t af[2][4];
            #pragma unroll
            for (int mt = 0; mt < 2; mt++) {
                const __nv_bfloat16* ap = As[cur] + (wm*32 + mt*16 + (lane & 15))*40
                                             + ks*16 + ((lane >> 4) & 1)*8;
                uint32_t addr = smem_u32(ap);
                asm volatile("ldmatrix.sync.aligned.m8n8.x4.shared.b16 {%0,%1,%2,%3}, [%4];"
                    : "=r"(af[mt][0]), "=r"(af[mt][1]), "=r"(af[mt][2]), "=r"(af[mt][3])
                    : "r"(addr));
            }
            #pragma unroll
            for (int ng = 0; ng < 4; ng++) {
                const __nv_bfloat16* bp = Bs[cur] + (ks*16 + (lane & 7) + ((lane >> 3) & 1)*8)*136
                                             + wn*64 + ng*16 + ((lane >> 4) & 1)*8;
                uint32_t addr = smem_u32(bp);
                uint32_t bf4[4];
                asm volatile("ldmatrix.sync.aligned.m8n8.x4.trans.shared.b16 {%0,%1,%2,%3}, [%4];"
                    : "=r"(bf4[0]), "=r"(bf4[1]), "=r"(bf4[2]), "=r"(bf4[3])
                    : "r"(addr));
                mma_bf16(acc[0][2*ng],   af[0], &bf4[0]);
                mma_bf16(acc[0][2*ng+1], af[0], &bf4[2]);
                mma_bf16(acc[1][2*ng],   af[1], &bf4[0]);
                mma_bf16(acc[1][2*ng+1], af[1], &bf4[2]);
            }
        }
        if (have_next) {
            // store next tile into the other buffer (no barrier needed: that
            // buffer's last readers finished before the previous sync)
            #pragma unroll
            for (int i = 0; i < 2; i++)
                *(uint4*)((uint32_t*)As[nxt] + (a_r + i*64)*20 + a_j*4) = pa[i];
            #pragma unroll
            for (int i = 0; i < 4; i++)
                *(uint2*)((uint32_t*)Bs[nxt] + (b_k + i*8)*68 + b_c*2) = pb[i];
            __syncthreads();
        }
    }

    float sc = *scale_p;
    int c = lane & 3, p = lane >> 2;
    #pragma unroll
    for (int mt = 0; mt < 2; mt++) {
        int r = row0 + wm*32 + mt*16 + p;
        #pragma unroll
        for (int nt = 0; nt < 8; nt++) {
            int cc = col0 + wn*64 + nt*8 + 2*c;
            float b0v = bias[cc], b1v = bias[cc + 1];
            size_t o1 = (size_t)r*256 + cc;
            float2 r1 = *(const float2*)(res + o1);
            float2 w1;
            w1.x = r1.x + sc*(acc[mt][nt][0] + b0v);
            w1.y = r1.y + sc*(acc[mt][nt][1] + b1v);
            *(float2*)(out + o1) = w1;
            size_t o2 = o1 + 8*256;
            float2 r2 = *(const float2*)(res + o2);
            float2 w2;
            w2.x = r2.x + sc*(acc[mt][nt][2] + b0v);
            w2.y = r2.y + sc*(acc[mt][nt][3] + b1v);
            *(float2*)(out + o2) = w2;
        }
    }
}

// ---------------- launch -----------------------------------------------------
extern "C" void kernel_launch(void* const* d_in, const int* in_sizes, int n_in,
                              void* d_out, int out_size) {
    const float* x     = (const float*)d_in[0];
    const float* bn1_g = (const float*)d_in[1];
    const float* bn1_b = (const float*)d_in[2];
    const float* Wqkv  = (const float*)d_in[3];
    const float* bqkv  = (const float*)d_in[4];
    const float* Wo    = (const float*)d_in[5];
    const float* bo    = (const float*)d_in[6];
    const float* bn2_g = (const float*)d_in[7];
    const float* bn2_b = (const float*)d_in[8];
    const float* W1    = (const float*)d_in[9];
    const float* b1    = (const float*)d_in[10];
    const float* W2    = (const float*)d_in[11];
    const float* b2    = (const float*)d_in[12];
    const float* scale = (const float*)d_in[13];
    float* out = (float*)d_out;

    float *p_x1;
    __nv_bfloat16 *p_attn, *p_h, *p_w1bf, *p_wobf, *p_w2bf;
    cudaGetSymbolAddress((void**)&p_x1,   g_x1);
    cudaGetSymbolAddress((void**)&p_attn, g_attn);
    cudaGetSymbolAddress((void**)&p_h,    g_h);
    cudaGetSymbolAddress((void**)&p_w1bf, g_w1bf);
    cudaGetSymbolAddress((void**)&p_wobf, g_wobf);
    cudaGetSymbolAddress((void**)&p_w2bf, g_w2bf);

    // convert W1 / Wo / W2 -> bf16
    cvtW<<<(DIM*HID/4)/256, 256>>>(W1, p_w1bf);
    cvtW<<<(DIM*DIM/4)/256, 256>>>(Wo, p_wobf);
    cvtW<<<(HID*DIM/4)/256, 256>>>(W2, p_w2bf);

    // stage 1: bn1 + LIF -> mask
    stats1<<<512, 256>>>(x);
    stats2<<<256, 256>>>();
    bnlif<<<(BB*LL*DIM)/256, 256>>>(x, bn1_g, bn1_b);

    // qkv (bf16 out) = s1 @ Wqkv + bqkv
    spgemm_qkv<<<NROWS, 256>>>(Wqkv, bqkv);

    // region means from spike counts (exact), affinity, top-k, attention
    regqk<<<64, 256>>>(Wqkv, bqkv);
    afftopk<<<32, 256>>>();
    attn_mma<<<LT*BB*RR*HEADS, 64>>>();

    // x1 = x + scale * (attn @ Wo + bo)
    dim3 gg(2, NROWS/128);
    gemm_bf16_res<<<gg, 256>>>(p_attn, p_wobf, bo, x, scale, p_x1, DIM);

    // stage 2: bn2 + LIF -> mask
    stats1<<<512, 256>>>(p_x1);
    stats2<<<256, 256>>>();
    bnlif<<<(BB*LL*DIM)/256, 256>>>(p_x1, bn2_g, bn2_b);

    // h = gelu(s2 @ W1 + b1)
    spgemm_mlp<<<NROWS, 256>>>(b1, p_h);

    // out = x1 + scale * (h @ W2 + b2)
    gemm_bf16_res<<<gg, 256>>>(p_h, p_w2bf, b2, p_x1, scale, out, HID);
}

// round 17
// speedup vs baseline: 1.0397x; 1.0397x over previous
#include <cuda_runtime.h>
#include <cuda_bf16.h>
#include <math.h>
#include <stdint.h>

#define LT   4
#define BB   8
#define LL   1024
#define DIM  256
#define NROWS (LT*BB*LL)     // 32768
#define HEADS 8
#define HD    32
#define RS    64
#define RR    16
#define NTOPK 4
#define QKVC  768
#define HID   1024

// ---------------- scratch ----------------------------------------------------
__device__ unsigned g_mask[NROWS*8];            // spike bitmasks (256 bits/row)
__device__ __nv_bfloat16 g_qkvb[NROWS*QKVC];    // q|k|v in bf16
__device__ float g_qr  [LT*BB*RR*DIM];
__device__ float g_kr  [LT*BB*RR*DIM];
__device__ int   g_idx [LT*BB*RR*NTOPK];
__device__ __nv_bfloat16 g_attn[NROWS*DIM];
__device__ float g_x1  [NROWS*DIM];
__device__ __nv_bfloat16 g_h   [NROWS*HID];
__device__ __nv_bfloat16 g_w1bf[DIM*HID];
__device__ __nv_bfloat16 g_wobf[DIM*DIM];
__device__ __nv_bfloat16 g_w2bf[HID*DIM];
__device__ float g_psum[512*DIM];
__device__ float g_psq [512*DIM];
__device__ float g_mean[DIM];
__device__ float g_var [DIM];

__device__ __forceinline__ uint32_t pk2(float a, float b) {
    __nv_bfloat162 h = __floats2bfloat162_rn(a, b);
    return *(uint32_t*)&h;
}
__device__ __forceinline__ uint32_t smem_u32(const void* p) {
    return (uint32_t)__cvta_generic_to_shared(p);
}

// ---------------- batchnorm stats (512 blocks x 64 rows) --------------------
__global__ void stats1(const float* __restrict__ in) {
    int blk = blockIdx.x, d = threadIdx.x;
    float s = 0.f, sq = 0.f;
    int r0 = blk * 64;
    for (int i = 0; i < 64; i++) {
        float v = in[(size_t)(r0 + i) * DIM + d];
        s += v; sq += v * v;
    }
    g_psum[blk*DIM + d] = s;
    g_psq [blk*DIM + d] = sq;
}

// parallel final reduce: one block per channel d, folds 512 partials
__global__ void stats2() {
    int d = blockIdx.x, t = threadIdx.x;
    __shared__ float ss[256];
    __shared__ float sq[256];
    ss[t] = g_psum[t*DIM + d] + g_psum[(t+256)*DIM + d];
    sq[t] = g_psq [t*DIM + d] + g_psq [(t+256)*DIM + d];
    __syncthreads();
    #pragma unroll
    for (int o = 128; o > 0; o >>= 1) {
        if (t < o) { ss[t] += ss[t + o]; sq[t] += sq[t + o]; }
        __syncthreads();
    }
    if (t == 0) {
        float mu = ss[0] / (float)NROWS;
        float var = sq[0] / (float)NROWS - mu * mu;
        g_mean[d] = mu;
        g_var[d]  = var > 0.f ? var : 0.f;
    }
}

// ---------------- batchnorm + LIF -> spike bitmask ---------------------------
__global__ void bnlif(const float* __restrict__ in,
                      const float* __restrict__ gamma,
                      const float* __restrict__ beta) {
    int tid = blockIdx.x * 256 + threadIdx.x;
    int d = tid & 255;
    int n = tid >> 8;
    float mu = g_mean[d];
    float iv = 1.0f / sqrtf(g_var[d] + 1e-5f);
    float ga = gamma[d], be = beta[d];
    const size_t stride = (size_t)BB * LL * DIM;
    size_t base = (size_t)tid;
    float v = 0.f;
    #pragma unroll
    for (int t = 0; t < LT; t++) {
        float xt = (in[base + t*stride] - mu) * iv * ga + be;
        v += (xt - v) * 0.5f;
        bool sp = (v >= 1.0f);
        unsigned m = __ballot_sync(0xffffffffu, sp);
        if (sp) v = 0.f;
        if ((d & 31) == 0)
            g_mask[((size_t)(t*8192 + n))*8 + (d >> 5)] = m;
    }
}

// ---------------- fp32 -> bf16 weight conversion ----------------------------
__global__ void cvtW(const float* __restrict__ src, __nv_bfloat16* __restrict__ dst) {
    int i = blockIdx.x * 256 + threadIdx.x;
    float4 v = ((const float4*)src)[i];
    uint2 o;
    o.x = pk2(v.x, v.y);
    o.y = pk2(v.z, v.w);
    ((uint2*)dst)[i] = o;
}

// ---------------- shared list-build from mask --------------------------------
__device__ __forceinline__ int build_list(int n, int tid, int* list,
                                          unsigned* masks, int* offs) {
    int warp = tid >> 5, lane = tid & 31;
    unsigned m = g_mask[(size_t)n * 8 + warp];
    if (lane == 0) masks[warp] = m;
    __syncthreads();
    if (tid == 0) {
        int o = 0;
        #pragma unroll
        for (int w = 0; w < 8; w++) { offs[w] = o; o += __popc(masks[w]); }
        offs[8] = o;
    }
    __syncthreads();
    if ((m >> lane) & 1)
        list[offs[warp] + __popc(m & ((1u << lane) - 1u))] = tid;
    int cnt = offs[8];
    __syncthreads();
    return cnt;
}

// ---------------- sparse binary GEMM: qkv (fp32 W gather, bf16 out) ---------
__global__ void spgemm_qkv(const float* __restrict__ W,
                           const float* __restrict__ bias) {
    int n = blockIdx.x, tid = threadIdx.x;
    __shared__ int list[256];
    __shared__ unsigned masks[8];
    __shared__ int offs[9];
    int cnt = build_list(n, tid, list, masks, offs);

    if (tid < 192) {
        const float4* W4 = (const float4*)W;
        float4 acc = ((const float4*)bias)[tid];
        for (int i = 0; i < cnt; i++) {
            float4 w = W4[(size_t)list[i] * 192 + tid];
            acc.x += w.x; acc.y += w.y; acc.z += w.z; acc.w += w.w;
        }
        uint2 o;
        o.x = pk2(acc.x, acc.y);
        o.y = pk2(acc.z, acc.w);
        ((uint2*)(g_qkvb + (size_t)n * QKVC))[tid] = o;
    }
}

// ---------------- sparse binary GEMM: MLP (bf16 W, bf16 out, gelu) ----------
__global__ void spgemm_mlp(const float* __restrict__ bias,
                           __nv_bfloat16* __restrict__ out) {
    int n = blockIdx.x, tid = threadIdx.x;
    __shared__ int list[256];
    __shared__ unsigned masks[8];
    __shared__ int offs[9];
    int cnt = build_list(n, tid, list, masks, offs);

    float4 bv = ((const float4*)bias)[tid];
    float a0 = bv.x, a1 = bv.y, a2 = bv.z, a3 = bv.w;
    for (int i = 0; i < cnt; i++) {
        uint2 w = *(const uint2*)(g_w1bf + (size_t)list[i] * HID + tid * 4);
        float2 f0 = __bfloat1622float2(*(__nv_bfloat162*)&w.x);
        float2 f1 = __bfloat1622float2(*(__nv_bfloat162*)&w.y);
        a0 += f0.x; a1 += f0.y; a2 += f1.x; a3 += f1.y;
    }
    a0 = 0.5f*a0*(1.f + erff(a0*0.70710678118654752f));
    a1 = 0.5f*a1*(1.f + erff(a1*0.70710678118654752f));
    a2 = 0.5f*a2*(1.f + erff(a2*0.70710678118654752f));
    a3 = 0.5f*a3*(1.f + erff(a3*0.70710678118654752f));
    uint2 o;
    o.x = pk2(a0, a1);
    o.y = pk2(a2, a3);
    ((uint2*)(out + (size_t)n * HID))[tid] = o;
}

// ---------------- region q/k means from spike counts (exact fp32) -----------
__global__ void regqk(const float* __restrict__ Wqkv,
                      const float* __restrict__ bqkv) {
    int blk = blockIdx.x, tid = threadIdx.x;
    int tb = blk >> 1, half = blk & 1;
    __shared__ unsigned words[8][64][8];   // 16 KB
    __shared__ float cntf[8][256];         // 8 KB
    int base_row = tb * 1024 + half * 512;
    for (int i = tid; i < 4096; i += 256) {
        int r = i >> 9, rem = i & 511, row = rem >> 3, w = rem & 7;
        words[r][row][w] = g_mask[(size_t)(base_row + r*64 + row)*8 + w];
    }
    __syncthreads();
    int wsel = tid >> 5, bit = tid & 31;
    #pragma unroll
    for (int r = 0; r < 8; r++) {
        int c = 0;
        #pragma unroll 16
        for (int i = 0; i < 64; i++) c += (words[r][i][wsel] >> bit) & 1;
        cntf[r][tid] = (float)c;
    }
    __syncthreads();
    float aq[8], ak[8];
    #pragma unroll
    for (int r = 0; r < 8; r++) { aq[r] = 0.f; ak[r] = 0.f; }
    for (int d = 0; d < 256; d++) {
        float wq = Wqkv[d*QKVC + tid];
        float wk = Wqkv[d*QKVC + 256 + tid];
        #pragma unroll
        for (int r = 0; r < 8; r++) {
            float c = cntf[r][d];
            aq[r] = fmaf(c, wq, aq[r]);
            ak[r] = fmaf(c, wk, ak[r]);
        }
    }
    float bq = bqkv[tid], bk = bqkv[256 + tid];
    #pragma unroll
    for (int r = 0; r < 8; r++) {
        int reg = tb*16 + half*8 + r;
        g_qr[reg*256 + tid] = aq[r]*(1.f/64.f) + bq;
        g_kr[reg*256 + tid] = ak[r]*(1.f/64.f) + bk;
    }
}

// ---------------- region affinity + top-k -----------------------------------
__global__ void afftopk() {
    __shared__ float qs[16][257];
    __shared__ float ks[16][257];
    __shared__ float aff[16][17];
    int tb = blockIdx.x, tid = threadIdx.x;
    for (int idx = tid; idx < 16*256; idx += 256) {
        int rr = idx >> 8, d = idx & 255;
        qs[rr][d] = g_qr[(tb*16 + rr)*DIM + d];
        ks[rr][d] = g_kr[(tb*16 + rr)*DIM + d];
    }
    __syncthreads();
    int r = tid >> 4, s = tid & 15;
    float a = 0.f;
    #pragma unroll 8
    for (int d = 0; d < 256; d++) a += qs[r][d] * ks[s][d];
    aff[r][s] = a;
    __syncthreads();
    if (tid < 16) {
        float vals[16];
        #pragma unroll
        for (int s2 = 0; s2 < 16; s2++) vals[s2] = aff[tid][s2];
        #pragma unroll
        for (int m = 0; m < NTOPK; m++) {
            int best = 0; float bv = vals[0];
            #pragma unroll
            for (int s2 = 1; s2 < 16; s2++)
                if (vals[s2] > bv) { bv = vals[s2]; best = s2; }
            g_idx[(tb*16 + tid)*NTOPK + m] = best;
            vals[best] = -1e30f;
        }
    }
}

// ---------------- bf16 mma --------------------------------------------------
__device__ __forceinline__ void mma_bf16(float* d, const uint32_t* a, const uint32_t* b) {
    asm volatile(
        "mma.sync.aligned.m16n8k16.row.col.f32.bf16.bf16.f32 "
        "{%0,%1,%2,%3}, {%4,%5,%6,%7}, {%8,%9}, {%0,%1,%2,%3};\n"
        : "+f"(d[0]), "+f"(d[1]), "+f"(d[2]), "+f"(d[3])
        : "r"(a[0]), "r"(a[1]), "r"(a[2]), "r"(a[3]), "r"(b[0]), "r"(b[1]));
}

// exp(s/sqrt(32)) via exp2, degree-4, FMA-pipe only
__device__ __forceinline__ float fexp_sc(float s) {
    const float C = 0.17677669529663687f * 1.4426950408889634f;
    float y = s * C;
    float z = y + 12582912.f;
    float n = z - 12582912.f;
    float f = y - n;
    float p = 0.0096181291f;
    p = fmaf(p, f, 0.0555041087f);
    p = fmaf(p, f, 0.2402265069f);
    p = fmaf(p, f, 0.6931471806f);
    p = fmaf(p, f, 1.0f);
    return __int_as_float(__float_as_int(p) + (__float_as_int(z) << 23));
}

// ---------------- bi-level attention (tensor cores, ldmatrix B-frags) -------
__global__ void attn_mma() {
    int bid = blockIdx.x;
    int h  = bid & 7;
    int r  = (bid >> 3) & 15;
    int tb = bid >> 7;
    int t = threadIdx.x, lane = t & 31, w = t >> 5;

    __shared__ __align__(16) __nv_bfloat16 Ks[64*40];
    __shared__ __align__(16) __nv_bfloat16 Vs[64*40];

    int rlo  = lane >> 2;
    int qcol = (lane & 3) * 2;

    uint32_t qf[2][2][4];
    int qr_base = tb * LL + r * RS + w * 32;
    #pragma unroll
    for (int mt = 0; mt < 2; mt++) {
        #pragma unroll
        for (int kt = 0; kt < 2; kt++) {
            const __nv_bfloat16* qp = g_qkvb + (size_t)(qr_base + mt*16 + rlo) * QKVC + h*HD + kt*16 + qcol;
            qf[mt][kt][0] = *(const uint32_t*)(qp);
            qf[mt][kt][1] = *(const uint32_t*)(qp + 8*QKVC);
            qf[mt][kt][2] = *(const uint32_t*)(qp + 8);
            qf[mt][kt][3] = *(const uint32_t*)(qp + 8*QKVC + 8);
        }
    }

    float oacc[2][4][4];
    #pragma unroll
    for (int mt = 0; mt < 2; mt++)
        #pragma unroll
        for (int nt = 0; nt < 4; nt++)
            #pragma unroll
            for (int q = 0; q < 4; q++) oacc[mt][nt][q] = 0.f;
    float rs[2][2] = {{0.f,0.f},{0.f,0.f}};

    int ldrow = lane & 7;
    int ldsel = (lane >> 3) & 1;
    int vrow  = lane & 15;

    for (int reg = 0; reg < NTOPK; reg++) {
        int s = g_idx[(tb*RR + r)*NTOPK + reg];
        int kvbase = tb * LL + s * RS;
        // fill K and V tiles, both [j][d] layout, uint2 vectorized
        #pragma unroll
        for (int i = 0; i < 8; i++) {
            int flat = i*64 + t;          // 0..511
            int j  = flat >> 3;           // 0..63
            int d4 = (flat & 7) * 4;      // 0..28
            const __nv_bfloat16* kp = g_qkvb + (size_t)(kvbase + j)*QKVC + DIM + h*HD + d4;
            *(uint2*)&Ks[j*40 + d4] = *(const uint2*)kp;
            *(uint2*)&Vs[j*40 + d4] = *(const uint2*)(kp + DIM);
        }
        __syncthreads();

        float sacc[2][8][4];
        #pragma unroll
        for (int mt = 0; mt < 2; mt++)
            #pragma unroll
            for (int nt = 0; nt < 8; nt++)
                #pragma unroll
                for (int q = 0; q < 4; q++) sacc[mt][nt][q] = 0.f;

        // S = Q @ K^T  (B-fragments via ldmatrix.x2)
        #pragma unroll
        for (int kt = 0; kt < 2; kt++) {
            #pragma unroll
            for (int nt = 0; nt < 8; nt++) {
                uint32_t addr = smem_u32(&Ks[(nt*8 + ldrow)*40 + kt*16 + ldsel*8]);
                uint32_t bfr[2];
                asm volatile("ldmatrix.sync.aligned.m8n8.x2.shared.b16 {%0,%1}, [%2];"
                    : "=r"(bfr[0]), "=r"(bfr[1]) : "r"(addr));
                mma_bf16(sacc[0][nt], qf[0][kt], bfr);
                mma_bf16(sacc[1][nt], qf[1][kt], bfr);
            }
        }

        uint32_t pf[2][4][4];
        #pragma unroll
        for (int mt = 0; mt < 2; mt++) {
            #pragma unroll
            for (int nt = 0; nt < 8; nt++) {
                float e0 = fexp_sc(sacc[mt][nt][0]);
                float e1 = fexp_sc(sacc[mt][nt][1]);
                float e2 = fexp_sc(sacc[mt][nt][2]);
                float e3 = fexp_sc(sacc[mt][nt][3]);
                rs[mt][0] += e0 + e1;
                rs[mt][1] += e2 + e3;
                int kt2 = nt >> 1;
                if ((nt & 1) == 0) {
                    pf[mt][kt2][0] = pk2(e0, e1);
                    pf[mt][kt2][1] = pk2(e2, e3);
                } else {
                    pf[mt][kt2][2] = pk2(e0, e1);
                    pf[mt][kt2][3] = pk2(e2, e3);
                }
            }
        }

        // O += P @ V  (B-fragments via ldmatrix.x2.trans on [j][d] tile)
        #pragma unroll
        for (int kt2 = 0; kt2 < 4; kt2++) {
            #pragma unroll
            for (int nv = 0; nv < 4; nv++) {
                uint32_t addr = smem_u32(&Vs[(kt2*16 + vrow)*40 + nv*8]);
                uint32_t bfr[2];
                asm volatile("ldmatrix.sync.aligned.m8n8.x2.trans.shared.b16 {%0,%1}, [%2];"
                    : "=r"(bfr[0]), "=r"(bfr[1]) : "r"(addr));
                mma_bf16(oacc[0][nv], pf[0][kt2], bfr);
                mma_bf16(oacc[1][nv], pf[1][kt2], bfr);
            }
        }
        __syncthreads();
    }

    #pragma unroll
    for (int mt = 0; mt < 2; mt++)
        #pragma unroll
        for (int i = 0; i < 2; i++) {
            float v = rs[mt][i];
            v += __shfl_xor_sync(0xffffffffu, v, 1);
            v += __shfl_xor_sync(0xffffffffu, v, 2);
            rs[mt][i] = 1.f / v;
        }

    #pragma unroll
    for (int mt = 0; mt < 2; mt++) {
        int row0 = qr_base + mt*16 + rlo;
        #pragma unroll
        for (int nv = 0; nv < 4; nv++) {
            int d = h*HD + nv*8 + qcol;
            *(uint32_t*)(g_attn + (size_t)row0*DIM + d) =
                pk2(oacc[mt][nv][0]*rs[mt][0], oacc[mt][nv][1]*rs[mt][0]);
            *(uint32_t*)(g_attn + (size_t)(row0+8)*DIM + d) =
                pk2(oacc[mt][nv][2]*rs[mt][1], oacc[mt][nv][3]*rs[mt][1]);
        }
    }
}

// ---------------- bf16 tensor-core GEMM, double-buffered smem ----------------
// out[M,256] = res + scale * (A_bf16[M,K] @ B_bf16[K,256] + bias)
__global__ void gemm_bf16_res(const __nv_bfloat16* __restrict__ A,
                              const __nv_bfloat16* __restrict__ B,
                              const float* __restrict__ bias,
                              const float* __restrict__ res,
                              const float* __restrict__ scale_p,
                              float* __restrict__ out,
                              int K) {
    __shared__ __align__(16) __nv_bfloat16 As[2][128*40];
    __shared__ __align__(16) __nv_bfloat16 Bs[2][32*136];
    int t = threadIdx.x;
    int lane = t & 31, warp = t >> 5;
    int wm = warp & 3;
    int wn = warp >> 2;
    int row0 = blockIdx.y * 128, col0 = blockIdx.x * 128;

    float acc[2][8][4];
    #pragma unroll
    for (int mt = 0; mt < 2; mt++)
        #pragma unroll
        for (int nt = 0; nt < 8; nt++)
            #pragma unroll
            for (int q = 0; q < 4; q++) acc[mt][nt][q] = 0.f;

    const __nv_bfloat16* Ag = A + (size_t)row0 * K;
    const __nv_bfloat16* Bg = B + col0;

    int a_r  = t >> 2, a_j = t & 3;
    int b_k  = t >> 5, b_c = t & 31;

    {
        uint4 pa[2];
        uint2 pb[4];
        #pragma unroll
        for (int i = 0; i < 2; i++)
            pa[i] = *(const uint4*)(Ag + (size_t)(a_r + i*64)*K + a_j*8);
        #pragma unroll
        for (int i = 0; i < 4; i++)
            pb[i] = *(const uint2*)(Bg + (size_t)(b_k + i*8)*256 + b_c*4);
        #pragma unroll
        for (int i = 0; i < 2; i++)
            *(uint4*)((uint32_t*)As[0] + (a_r + i*64)*20 + a_j*4) = pa[i];
        #pragma unroll
        for (int i = 0; i < 4; i++)
            *(uint2*)((uint32_t*)Bs[0] + (b_k + i*8)*68 + b_c*2) = pb[i];
    }
    __syncthreads();

    int nkt = K >> 5;
    for (int kt = 0; kt < nkt; kt++) {
        int cur = kt & 1, nxt = cur ^ 1;
        uint4 pa[2];
        uint2 pb[4];
        bool have_next = (kt + 1 < nkt);
        if (have_next) {
            int k0 = (kt + 1) * 32;
            #pragma unroll
            for (int i = 0; i < 2; i++)
                pa[i] = *(const uint4*)(Ag + (size_t)(a_r + i*64)*K + k0 + a_j*8);
            #pragma unroll
            for (int i = 0; i < 4; i++)
                pb[i] = *(const uint2*)(Bg + (size_t)(k0 + b_k + i*8)*256 + b_c*4);
        }
        #pragma unroll
        for (int ks = 0; ks < 2; ks++) {
            uint32_t af[2][4];
            #pragma unroll
            for (int mt = 0; mt < 2; mt++) {
                const __nv_bfloat16* ap = As[cur] + (wm*32 + mt*16 + (lane & 15))*40
                                             + ks*16 + ((lane >> 4) & 1)*8;
                uint32_t addr = smem_u32(ap);
                asm volatile("ldmatrix.sync.aligned.m8n8.x4.shared.b16 {%0,%1,%2,%3}, [%4];"
                    : "=r"(af[mt][0]), "=r"(af[mt][1]), "=r"(af[mt][2]), "=r"(af[mt][3])
                    : "r"(addr));
            }
            #pragma unroll
            for (int ng = 0; ng < 4; ng++) {
                const __nv_bfloat16* bp = Bs[cur] + (ks*16 + (lane & 7) + ((lane >> 3) & 1)*8)*136
                                             + wn*64 + ng*16 + ((lane >> 4) & 1)*8;
                uint32_t addr = smem_u32(bp);
                uint32_t bf4[4];
                asm volatile("ldmatrix.sync.aligned.m8n8.x4.trans.shared.b16 {%0,%1,%2,%3}, [%4];"
                    : "=r"(bf4[0]), "=r"(bf4[1]), "=r"(bf4[2]), "=r"(bf4[3])
                    : "r"(addr));
                mma_bf16(acc[0][2*ng],   af[0], &bf4[0]);
                mma_bf16(acc[0][2*ng+1], af[0], &bf4[2]);
                mma_bf16(acc[1][2*ng],   af[1], &bf4[0]);
                mma_bf16(acc[1][2*ng+1], af[1], &bf4[2]);
            }
        }
        if (have_next) {
            #pragma unroll
            for (int i = 0; i < 2; i++)
                *(uint4*)((uint32_t*)As[nxt] + (a_r + i*64)*20 + a_j*4) = pa[i];
            #pragma unroll
            for (int i = 0; i < 4; i++)
                *(uint2*)((uint32_t*)Bs[nxt] + (b_k + i*8)*68 + b_c*2) = pb[i];
            __syncthreads();
        }
    }

    float sc = *scale_p;
    int c = lane & 3, p = lane >> 2;
    #pragma unroll
    for (int mt = 0; mt < 2; mt++) {
        int r = row0 + wm*32 + mt*16 + p;
        #pragma unroll
        for (int nt = 0; nt < 8; nt++) {
            int cc = col0 + wn*64 + nt*8 + 2*c;
            float b0v = bias[cc], b1v = bias[cc + 1];
            size_t o1 = (size_t)r*256 + cc;
            float2 r1 = *(const float2*)(res + o1);
            float2 w1;
            w1.x = r1.x + sc*(acc[mt][nt][0] + b0v);
            w1.y = r1.y + sc*(acc[mt][nt][1] + b1v);
            *(float2*)(out + o1) = w1;
            size_t o2 = o1 + 8*256;
            float2 r2 = *(const float2*)(res + o2);
            float2 w2;
            w2.x = r2.x + sc*(acc[mt][nt][2] + b0v);
            w2.y = r2.y + sc*(acc[mt][nt][3] + b1v);
            *(float2*)(out + o2) = w2;
        }
    }
}

// ---------------- launch -----------------------------------------------------
extern "C" void kernel_launch(void* const* d_in, const int* in_sizes, int n_in,
                              void* d_out, int out_size) {
    const float* x     = (const float*)d_in[0];
    const float* bn1_g = (const float*)d_in[1];
    const float* bn1_b = (const float*)d_in[2];
    const float* Wqkv  = (const float*)d_in[3];
    const float* bqkv  = (const float*)d_in[4];
    const float* Wo    = (const float*)d_in[5];
    const float* bo    = (const float*)d_in[6];
    const float* bn2_g = (const float*)d_in[7];
    const float* bn2_b = (const float*)d_in[8];
    const float* W1    = (const float*)d_in[9];
    const float* b1    = (const float*)d_in[10];
    const float* W2    = (const float*)d_in[11];
    const float* b2    = (const float*)d_in[12];
    const float* scale = (const float*)d_in[13];
    float* out = (float*)d_out;

    float *p_x1;
    __nv_bfloat16 *p_attn, *p_h, *p_w1bf, *p_wobf, *p_w2bf;
    cudaGetSymbolAddress((void**)&p_x1,   g_x1);
    cudaGetSymbolAddress((void**)&p_attn, g_attn);
    cudaGetSymbolAddress((void**)&p_h,    g_h);
    cudaGetSymbolAddress((void**)&p_w1bf, g_w1bf);
    cudaGetSymbolAddress((void**)&p_wobf, g_wobf);
    cudaGetSymbolAddress((void**)&p_w2bf, g_w2bf);

    // convert W1 / Wo / W2 -> bf16
    cvtW<<<(DIM*HID/4)/256, 256>>>(W1, p_w1bf);
    cvtW<<<(DIM*DIM/4)/256, 256>>>(Wo, p_wobf);
    cvtW<<<(HID*DIM/4)/256, 256>>>(W2, p_w2bf);

    // stage 1: bn1 + LIF -> mask
    stats1<<<512, 256>>>(x);
    stats2<<<256, 256>>>();
    bnlif<<<(BB*LL*DIM)/256, 256>>>(x, bn1_g, bn1_b);

    // qkv (bf16 out) = s1 @ Wqkv + bqkv
    spgemm_qkv<<<NROWS, 256>>>(Wqkv, bqkv);

    // region means from spike counts (exact), affinity, top-k, attention
    regqk<<<64, 256>>>(Wqkv, bqkv);
    afftopk<<<32, 256>>>();
    attn_mma<<<LT*BB*RR*HEADS, 64>>>();

    // x1 = x + scale * (attn @ Wo + bo)
    dim3 gg(2, NROWS/128);
    gemm_bf16_res<<<gg, 256>>>(p_attn, p_wobf, bo, x, scale, p_x1, DIM);

    // stage 2: bn2 + LIF -> mask
    stats1<<<512, 256>>>(p_x1);
    stats2<<<256, 256>>>();
    bnlif<<<(BB*LL*DIM)/256, 256>>>(p_x1, bn2_g, bn2_b);

    // h = gelu(s2 @ W1 + b1)
    spgemm_mlp<<<NROWS, 256>>>(b1, p_h);

    // out = x1 + scale * (h @ W2 + b2)
    gemm_bf16_res<<<gg, 256>>>(p_h, p_w2bf, b2, p_x1, scale, out, HID);
}